// round 1
// baseline (speedup 1.0000x reference)
#include <cuda_runtime.h>

// SingleLayerLSTM: B=128, T=512, IN=128, H=1024, OUT=64.
// Persistent kernel, 128 CTAs x 256 threads, hand-rolled grid barrier.
// CTA (bt, hs): batch rows [bt*32, bt*32+32), hidden slice [hs*32, hs*32+32).
// Per step: CTA computes a 32x128 tile of pre-activations where the 128 cols
// are the 4 gates (f,i,z from kernel_fiz; r from kernel_r) for its hidden
// slice, so gate combination + cell update is CTA-local. c lives in registers
// for all 512 steps. h is double-buffered in a __device__ array (L2-coherent
// via __ldcg/__stcg + threadfence in the barrier).

#define BB 128
#define TT 512
#define IND 128
#define HH 1024
#define OUTD 64
#define NCTA 128
#define NTHR 256
#define KB 32
#define NCHUNK 36   // 1152 / 32

__device__ float g_h[2][BB * HH];          // double-buffered hidden state
__device__ unsigned int g_bar_count = 0;
__device__ unsigned int g_bar_gen = 0;

__device__ __forceinline__ float sigmoid_(float x) {
    return __fdividef(1.0f, 1.0f + __expf(-x));
}
__device__ __forceinline__ float tanh_(float x) {
    return __fdividef(2.0f, 1.0f + __expf(-2.0f * x)) - 1.0f;
}

// Sense-free monotonic-epoch grid barrier. All 128 CTAs are co-resident
// (grid=128 < 148 SMs, 1 CTA/SM). Arrive via device atomic; poll via
// volatile L2 load (no atomic hammering of one address).
__device__ __forceinline__ void grid_barrier(unsigned int& epoch) {
    __syncthreads();
    if (threadIdx.x == 0) {
        __threadfence();                       // release: h/y writes visible
        unsigned int target = epoch + 1;
        unsigned int arr = atomicAdd(&g_bar_count, 1u);
        if (arr == NCTA - 1) {
            atomicExch(&g_bar_count, 0u);
            __threadfence();
            atomicAdd(&g_bar_gen, 1u);
        } else {
            while ((int)(*(volatile unsigned int*)&g_bar_gen - target) < 0) {
                __nanosleep(64);
            }
        }
        epoch = target;
        __threadfence();                       // acquire
    }
    __syncthreads();
}

__global__ void __launch_bounds__(NTHR, 1)
lstm_kernel(const float* __restrict__ u,      // (B,T,IN)
            const float* __restrict__ x0,     // (B,1,2H)
            const float* __restrict__ kfiz,   // (1152, 3072)
            const float* __restrict__ bfiz,   // (3072)
            const float* __restrict__ kr,     // (1152, 1024)
            const float* __restrict__ br,     // (1024)
            const float* __restrict__ wout,   // (1024, 64)
            const float* __restrict__ bout,   // (64)
            float* __restrict__ y)            // (B,T,OUT)
{
    __shared__ float ws[KB][128];     // weight tile: [kk][gate*32 + cc]
    __shared__ float xs[KB][36];      // x tile: [kk][row], padded to 36 for LDS.128
    __shared__ float pre[32][128];    // pre-activations
    __shared__ float sred[NTHR];      // y reduction

    const int tid = threadIdx.x;
    const int bid = blockIdx.x;
    const int b0 = (bid >> 5) * 32;   // batch tile base
    const int hb = (bid & 31) * 32;   // hidden slice base

    // GEMM microtile: thread -> 4 rows x 4 cols of the 32x128 tile
    const int cb = (tid & 31) * 4;    // local col base (0..124)
    const int rb = (tid >> 5) * 4;    // local row base (0..28)

    // combine-phase mapping: thread -> (row crow, 4 hidden idx chh..chh+3)
    const int crow = tid >> 3;        // 0..31
    const int chh = (tid & 7) * 4;    // 0..28

    unsigned int epoch = 0;
    if (tid == 0) epoch = *(volatile unsigned int*)&g_bar_gen;

    // Init c (registers, persistent) and h buffer 0 from x0 = [h0 | c0]
    float4 c_reg = *(const float4*)&x0[(size_t)(b0 + crow) * (2 * HH) + HH + hb + chh];
    {
        float4 h0 = *(const float4*)&x0[(size_t)(b0 + crow) * (2 * HH) + hb + chh];
        __stcg((float4*)&g_h[0][(b0 + crow) * HH + hb + chh], h0);
    }

    // Per-thread bias for its 4 output columns (same for all rows)
    const int bgate = cb >> 5;
    const int bcc = cb & 31;
    float4 biasv = (bgate < 3) ? *(const float4*)&bfiz[bgate * HH + hb + bcc]
                               : *(const float4*)&br[hb + bcc];

    // Weight-load addressing (constant across steps)
    const int wkk0 = tid >> 5;                // kk base (0..7), +0/8/16/24
    const int wcol = (tid & 31) * 4;          // tile col (0..124)
    const int wg = wcol >> 5;                 // gate 0..3
    const int wcc = wcol & 31;
    const float* wbase = (wg < 3) ? (kfiz + wg * HH + hb + wcc) : (kr + hb + wcc);
    const int wstride = (wg < 3) ? (3 * HH) : HH;

    grid_barrier(epoch);   // h0 visible to all CTAs

    float4 wreg[4];
    float xreg[4];

    for (int t = 0; t < TT; ++t) {
        const float* hcur = g_h[t & 1];
        float* hnext = g_h[(t + 1) & 1];

        float acc[4][4];
        #pragma unroll
        for (int i = 0; i < 4; ++i) {
            acc[i][0] = biasv.x; acc[i][1] = biasv.y;
            acc[i][2] = biasv.z; acc[i][3] = biasv.w;
        }

        // ---- prefetch chunk 0 (k in [0,32): always from u) ----
        {
            #pragma unroll
            for (int i = 0; i < 4; ++i) {
                int k = wkk0 + i * 8;
                wreg[i] = *(const float4*)(wbase + (size_t)k * wstride);
            }
            int kx = tid & 31;
            int r0 = tid >> 5;
            #pragma unroll
            for (int i = 0; i < 4; ++i) {
                int r = r0 + i * 8;
                xreg[i] = u[((size_t)(b0 + r) * TT + t) * IND + kx];
            }
        }

        for (int c = 0; c < NCHUNK; ++c) {
            // store prefetched chunk to smem
            #pragma unroll
            for (int i = 0; i < 4; ++i)
                *(float4*)&ws[wkk0 + i * 8][wcol] = wreg[i];
            {
                int kk = tid & 31;
                int r0 = tid >> 5;
                #pragma unroll
                for (int i = 0; i < 4; ++i)
                    xs[kk][r0 + i * 8] = xreg[i];
            }
            __syncthreads();

            // issue next chunk's global loads (latency hidden by compute)
            if (c + 1 < NCHUNK) {
                const int k0 = (c + 1) * KB;
                #pragma unroll
                for (int i = 0; i < 4; ++i) {
                    int k = k0 + wkk0 + i * 8;
                    wreg[i] = *(const float4*)(wbase + (size_t)k * wstride);
                }
                int kx = k0 + (tid & 31);
                int r0 = tid >> 5;
                #pragma unroll
                for (int i = 0; i < 4; ++i) {
                    int r = r0 + i * 8;
                    if (kx < IND)
                        xreg[i] = u[((size_t)(b0 + r) * TT + t) * IND + kx];
                    else
                        xreg[i] = __ldcg(&hcur[(b0 + r) * HH + (kx - IND)]);
                }
            }

            // compute 32 k-iterations from smem
            #pragma unroll 8
            for (int kk = 0; kk < KB; ++kk) {
                float4 wv = *(float4*)&ws[kk][cb];
                float4 xv = *(float4*)&xs[kk][rb];
                acc[0][0] += xv.x * wv.x; acc[0][1] += xv.x * wv.y;
                acc[0][2] += xv.x * wv.z; acc[0][3] += xv.x * wv.w;
                acc[1][0] += xv.y * wv.x; acc[1][1] += xv.y * wv.y;
                acc[1][2] += xv.y * wv.z; acc[1][3] += xv.y * wv.w;
                acc[2][0] += xv.z * wv.x; acc[2][1] += xv.z * wv.y;
                acc[2][2] += xv.z * wv.z; acc[2][3] += xv.z * wv.w;
                acc[3][0] += xv.w * wv.x; acc[3][1] += xv.w * wv.y;
                acc[3][2] += xv.w * wv.z; acc[3][3] += xv.w * wv.w;
            }
            __syncthreads();
        }

        // ---- pre-activations to smem ----
        #pragma unroll
        for (int i = 0; i < 4; ++i) {
            float4 v = make_float4(acc[i][0], acc[i][1], acc[i][2], acc[i][3]);
            *(float4*)&pre[rb + i][cb] = v;
        }
        __syncthreads();

        // ---- gate combine + cell update (c register-resident) ----
        {
            float4 fv = *(float4*)&pre[crow][chh];
            float4 iv = *(float4*)&pre[crow][32 + chh];
            float4 zv = *(float4*)&pre[crow][64 + chh];
            float4 rv = *(float4*)&pre[crow][96 + chh];
            float4 hn;
            c_reg.x = sigmoid_(fv.x) * c_reg.x + sigmoid_(iv.x) * tanh_(rv.x);
            hn.x = sigmoid_(zv.x) * tanh_(c_reg.x);
            c_reg.y = sigmoid_(fv.y) * c_reg.y + sigmoid_(iv.y) * tanh_(rv.y);
            hn.y = sigmoid_(zv.y) * tanh_(c_reg.y);
            c_reg.z = sigmoid_(fv.z) * c_reg.z + sigmoid_(iv.z) * tanh_(rv.z);
            hn.z = sigmoid_(zv.z) * tanh_(c_reg.z);
            c_reg.w = sigmoid_(fv.w) * c_reg.w + sigmoid_(iv.w) * tanh_(rv.w);
            hn.w = sigmoid_(zv.w) * tanh_(c_reg.w);
            __stcg((float4*)&hnext[(b0 + crow) * HH + hb + chh], hn);
        }

        // ---- y(t-1) = h(t-1) @ W_out + b_out; CTA bid handles batch row bid
        if (t > 0) {
            const float* hrow = &hcur[bid * HH];
            int o = tid & 63;
            int kbas = (tid >> 6) * 256;
            float p = 0.0f;
            #pragma unroll 4
            for (int i = 0; i < 256; ++i) {
                p += __ldcg(&hrow[kbas + i]) * wout[(kbas + i) * OUTD + o];
            }
            sred[tid] = p;
            __syncthreads();
            if (tid < 64) {
                float s = sred[tid] + sred[tid + 64] + sred[tid + 128] + sred[tid + 192]
                        + bout[tid];
                y[((size_t)bid * TT + (t - 1)) * OUTD + tid] = s;
            }
        }

        grid_barrier(epoch);
    }

    // ---- final y(T-1) from g_h[0] (= h after step 511) ----
    {
        const float* hrow = &g_h[0][bid * HH];
        int o = tid & 63;
        int kbas = (tid >> 6) * 256;
        float p = 0.0f;
        #pragma unroll 4
        for (int i = 0; i < 256; ++i) {
            p += __ldcg(&hrow[kbas + i]) * wout[(kbas + i) * OUTD + o];
        }
        sred[tid] = p;
        __syncthreads();
        if (tid < 64) {
            float s = sred[tid] + sred[tid + 64] + sred[tid + 128] + sred[tid + 192]
                    + bout[tid];
            y[((size_t)bid * TT + (TT - 1)) * OUTD + tid] = s;
        }
    }
}

extern "C" void kernel_launch(void* const* d_in, const int* in_sizes, int n_in,
                              void* d_out, int out_size) {
    (void)in_sizes; (void)n_in; (void)out_size;
    lstm_kernel<<<NCTA, NTHR>>>(
        (const float*)d_in[0],   // u
        (const float*)d_in[1],   // x0
        (const float*)d_in[2],   // kernel_fiz
        (const float*)d_in[3],   // bias_fiz
        (const float*)d_in[4],   // kernel_r
        (const float*)d_in[5],   // bias_r
        (const float*)d_in[6],   // W_out
        (const float*)d_in[7],   // b_out
        (float*)d_out);
}